// round 14
// baseline (speedup 1.0000x reference)
#include <cuda_runtime.h>
#include <cuda_bf16.h>
#include <math.h>
#include <stdint.h>

#define BB 16
#define SS 2048
#define CC 512

// ---------------------------------------------------------------------------
// Device-global scratch (allocation-free per harness rules)
// ---------------------------------------------------------------------------
__device__ __nv_bfloat16 g_txh[BB*SS*CC], g_txl[BB*SS*CC];   // tanh(x') hi/lo
__device__ __nv_bfloat16 g_xph[BB*SS*CC], g_xpl[BB*SS*CC];   // x' hi/lo
__device__ __nv_bfloat16 g_wh[CC*CC],     g_wl[CC*CC];       // W hi/lo
__device__ __nv_bfloat16 g_qh[BB*SS*CC],  g_ql[BB*SS*CC];    // q hi/lo
__device__ __nv_bfloat16 g_xth[BB*SS*CC], g_xtl[BB*SS*CC];   // x^T hi/lo [b][c][t]
__device__ float         g_score[(size_t)BB*SS*SS];          // 268 MB
__device__ __nv_bfloat16 g_ah[(size_t)BB*SS*SS], g_al[(size_t)BB*SS*SS]; // alpha hi/lo

// ---------------------------------------------------------------------------
// PTX helpers (plain-sm_103-legal: ldmatrix, mma.sync, cp.async)
// ---------------------------------------------------------------------------
__device__ __forceinline__ uint32_t smem_u32(const void* p) {
    uint32_t a;
    asm("{ .reg .u64 t; cvta.to.shared.u64 t, %1; cvt.u32.u64 %0, t; }" : "=r"(a) : "l"(p));
    return a;
}
__device__ __forceinline__ void ldsm_x4(uint32_t* r, uint32_t addr) {
    asm volatile("ldmatrix.sync.aligned.m8n8.x4.shared.b16 {%0,%1,%2,%3}, [%4];"
        : "=r"(r[0]), "=r"(r[1]), "=r"(r[2]), "=r"(r[3]) : "r"(addr));
}
__device__ __forceinline__ void mma16816(float* d, const uint32_t* a, const uint32_t* b) {
    asm volatile(
        "mma.sync.aligned.m16n8k16.row.col.f32.bf16.bf16.f32 "
        "{%0,%1,%2,%3}, {%4,%5,%6,%7}, {%8,%9}, {%0,%1,%2,%3};"
        : "+f"(d[0]), "+f"(d[1]), "+f"(d[2]), "+f"(d[3])
        : "r"(a[0]), "r"(a[1]), "r"(a[2]), "r"(a[3]), "r"(b[0]), "r"(b[1]));
}
__device__ __forceinline__ void cp16(uint32_t s, const void* g) {
    asm volatile("cp.async.cg.shared.global [%0], [%1], 16;" :: "r"(s), "l"(g));
}
#define CP_COMMIT()  asm volatile("cp.async.commit_group;" ::: "memory")
#define CP_WAIT(n)   asm volatile("cp.async.wait_group %0;" :: "n"(n) : "memory")

// ---------------------------------------------------------------------------
// GEMM: C[M,N] = (Ah+Al)[M,K] * (Bh+Bl)[N,K]^T, bf16x3 (drop lo*lo), fp32 acc.
// CTA tile 128x128, K chunks of 32, double-buffered cp.async, 256 threads.
// Warps 4x2 -> 32x64 warp tile. B frags double-buffered in regs; MMA passes
// emitted pass-major so same-accumulator MMAs sit 4 independent issues apart.
// Rows padded to 40 bf16 (80B, conflict-free for ldmatrix).
// EPI: 0 = +bias then split to (Ch,Cl) bf16 ; 1 = fp32 to Cf ; 2 = tanh to Cf.
// ---------------------------------------------------------------------------
#define TM 128
#define TN 128
#define TK 32
#define ROWB 80                       // padded row bytes (40 bf16)
#define A_HALF (TM * ROWB)            // 10240
#define B_HALF (TN * ROWB)            // 10240
#define STAGE (2*A_HALF + 2*B_HALF)   // 40960
#define GEMM_SMEM (2 * STAGE)         // 81920

template<int EPI>
__global__ void __launch_bounds__(256, 2)
gemm_nt(const __nv_bfloat16* __restrict__ Ah, const __nv_bfloat16* __restrict__ Al,
        const __nv_bfloat16* __restrict__ Bh, const __nv_bfloat16* __restrict__ Bl,
        float* __restrict__ Cf,
        __nv_bfloat16* __restrict__ Ch, __nv_bfloat16* __restrict__ Cl,
        const float* __restrict__ bias,
        int M, int N, int K, long sA, long sB, long sC)
{
    extern __shared__ __align__(16) char smem[];
    const uint32_t sb = smem_u32(smem);

    const int tid = threadIdx.x;
    const long z = blockIdx.z;
    const int bm = blockIdx.y * TM;
    const int bn = blockIdx.x * TN;
    const __nv_bfloat16* Ahb = Ah + z * sA;
    const __nv_bfloat16* Alb = Al + z * sA;
    const __nv_bfloat16* Bhb = Bh + z * sB;
    const __nv_bfloat16* Blb = Bl + z * sB;

    // --- async stage loader: 8 x 16B per thread ---
    auto load_stage = [&](int kk, int s) {
        const uint32_t st = sb + s * STAGE;
#pragma unroll
        for (int i = 0; i < 4; i++) {                 // A hi/lo: 1024 chunks
            int idx = tid + i * 256;
            int half = idx >> 9;
            int row  = (idx & 511) >> 2;
            int ch   = idx & 3;
            const __nv_bfloat16* src =
                (half ? Alb : Ahb) + (long)(bm + row) * K + kk + ch * 8;
            cp16(st + half * A_HALF + row * ROWB + ch * 16, src);
        }
#pragma unroll
        for (int i = 0; i < 4; i++) {                 // B hi/lo: 1024 chunks
            int idx = tid + i * 256;
            int half = idx >> 9;
            int row  = (idx & 511) >> 2;
            int ch   = idx & 3;
            const __nv_bfloat16* src =
                (half ? Blb : Bhb) + (long)(bn + row) * K + kk + ch * 8;
            cp16(st + 2 * A_HALF + half * B_HALF + row * ROWB + ch * 16, src);
        }
    };

    const int w  = tid >> 5, l = tid & 31;
    const int wr = (w >> 1) * 32;        // warp row offset (4 rows of warps)
    const int wc = (w & 1) * 64;         // warp col offset (2 cols of warps)

    // lane-derived ldmatrix offsets
    const uint32_t a_loff = (l & 15) * ROWB + (l >> 4) * 16;
    const uint32_t b_loff = (((l >> 4) & 1) * 8 + (l & 7)) * ROWB + ((l >> 3) & 1) * 16;

    float acc[2][8][4];
#pragma unroll
    for (int mi = 0; mi < 2; mi++)
#pragma unroll
        for (int ni = 0; ni < 8; ni++)
#pragma unroll
            for (int j = 0; j < 4; j++) acc[mi][ni][j] = 0.0f;

    const int nc = K / TK;
    load_stage(0, 0);
    CP_COMMIT();

    for (int c = 0; c < nc; c++) {
        if (c + 1 < nc) {
            load_stage((c + 1) * TK, (c + 1) & 1);
            CP_COMMIT();
            CP_WAIT(1);
        } else {
            CP_WAIT(0);
        }
        __syncthreads();

        const uint32_t st = sb + (c & 1) * STAGE;
        const uint32_t a_h = st + (wr * ROWB) + a_loff;
        const uint32_t a_l = a_h + A_HALF;
        const uint32_t b_h = st + 2 * A_HALF + (wc * ROWB) + b_loff;
        const uint32_t b_l = b_h + B_HALF;

#pragma unroll
        for (int ks = 0; ks < 2; ks++) {
            uint32_t ah[2][4], al[2][4];
#pragma unroll
            for (int mi = 0; mi < 2; mi++) {
                ldsm_x4(ah[mi], a_h + mi * 16 * ROWB + ks * 32);
                ldsm_x4(al[mi], a_l + mi * 16 * ROWB + ks * 32);
            }
            // B fragments double-buffered across the 4 n16 groups
            uint32_t bh[2][4], bl[2][4];
            ldsm_x4(bh[0], b_h + ks * 32);
            ldsm_x4(bl[0], b_l + ks * 32);
#pragma unroll
            for (int p = 0; p < 4; p++) {
                const int cur = p & 1, nxt = cur ^ 1;
                if (p + 1 < 4) {
                    ldsm_x4(bh[nxt], b_h + (p + 1) * 16 * ROWB + ks * 32);
                    ldsm_x4(bl[nxt], b_l + (p + 1) * 16 * ROWB + ks * 32);
                }
                // pass-major: same-acc MMAs are 4 independent issues apart
#pragma unroll
                for (int s2 = 0; s2 < 2; s2++)            // hi*hi
#pragma unroll
                    for (int mi = 0; mi < 2; mi++)
                        mma16816(acc[mi][p * 2 + s2], ah[mi], &bh[cur][s2 * 2]);
#pragma unroll
                for (int s2 = 0; s2 < 2; s2++)            // hi*lo
#pragma unroll
                    for (int mi = 0; mi < 2; mi++)
                        mma16816(acc[mi][p * 2 + s2], ah[mi], &bl[cur][s2 * 2]);
#pragma unroll
                for (int s2 = 0; s2 < 2; s2++)            // lo*hi
#pragma unroll
                    for (int mi = 0; mi < 2; mi++)
                        mma16816(acc[mi][p * 2 + s2], al[mi], &bh[cur][s2 * 2]);
            }
        }
        __syncthreads();
    }

    // --- epilogue ---
#pragma unroll
    for (int mi = 0; mi < 2; mi++)
#pragma unroll
        for (int ni = 0; ni < 8; ni++) {
            const float* d = acc[mi][ni];
            const int r0 = bm + wr + mi * 16 + (l >> 2);
            const int c0 = bn + wc + ni * 8 + (l & 3) * 2;
#pragma unroll
            for (int h = 0; h < 2; h++) {
                const int row = r0 + h * 8;
                float v0 = d[h * 2], v1 = d[h * 2 + 1];
                if (EPI == 0) {
                    v0 += bias[c0]; v1 += bias[c0 + 1];
                    __nv_bfloat162 hp, lp;
                    hp.x = __float2bfloat16(v0);
                    hp.y = __float2bfloat16(v1);
                    lp.x = __float2bfloat16(v0 - __bfloat162float(hp.x));
                    lp.y = __float2bfloat16(v1 - __bfloat162float(hp.y));
                    long o = z * sC + (long)row * N + c0;
                    *(__nv_bfloat162*)(Ch + o) = hp;
                    *(__nv_bfloat162*)(Cl + o) = lp;
                } else {
                    if (EPI == 2) { v0 = tanhf(v0); v1 = tanhf(v1); }
                    *(float2*)(Cf + z * sC + (long)row * N + c0) = make_float2(v0, v1);
                }
            }
        }
}

// ---------------------------------------------------------------------------
// Elementwise splits
// ---------------------------------------------------------------------------
__device__ __forceinline__ void split2(float v, __nv_bfloat16& h, __nv_bfloat16& l) {
    h = __float2bfloat16(v);
    l = __float2bfloat16(v - __bfloat162float(h));
}

__global__ void split_xp_k(const float4* __restrict__ xp,
                           __nv_bfloat162* th, __nv_bfloat162* tl,
                           __nv_bfloat162* xh, __nv_bfloat162* xl, int n4)
{
    int i = blockIdx.x * blockDim.x + threadIdx.x;
    if (i >= n4) return;
    float4 v = xp[i];
    __nv_bfloat162 a, b;
    split2(v.x, a.x, b.x); split2(v.y, a.y, b.y); xh[2*i] = a; xl[2*i] = b;
    split2(v.z, a.x, b.x); split2(v.w, a.y, b.y); xh[2*i+1] = a; xl[2*i+1] = b;
    float4 t = make_float4(tanhf(v.x), tanhf(v.y), tanhf(v.z), tanhf(v.w));
    split2(t.x, a.x, b.x); split2(t.y, a.y, b.y); th[2*i] = a; tl[2*i] = b;
    split2(t.z, a.x, b.x); split2(t.w, a.y, b.y); th[2*i+1] = a; tl[2*i+1] = b;
}

__global__ void split_w_k(const float4* __restrict__ w,
                          __nv_bfloat162* wh, __nv_bfloat162* wl, int n4)
{
    int i = blockIdx.x * blockDim.x + threadIdx.x;
    if (i >= n4) return;
    float4 v = w[i];
    __nv_bfloat162 a, b;
    split2(v.x, a.x, b.x); split2(v.y, a.y, b.y); wh[2*i] = a; wl[2*i] = b;
    split2(v.z, a.x, b.x); split2(v.w, a.y, b.y); wh[2*i+1] = a; wl[2*i+1] = b;
}

// x[b][t][c] -> xT[b][c][t] hi/lo
__global__ void transpose_split_x(const float* __restrict__ x,
                                  __nv_bfloat16* __restrict__ xh,
                                  __nv_bfloat16* __restrict__ xl)
{
    __shared__ float tile[32][33];
    const int b = blockIdx.z;
    const int t0 = blockIdx.x * 32, c0 = blockIdx.y * 32;
    const float* xb = x + (size_t)b * SS * CC;
#pragma unroll
    for (int i = threadIdx.y; i < 32; i += 8)
        tile[i][threadIdx.x] = xb[(size_t)(t0 + i) * CC + c0 + threadIdx.x];
    __syncthreads();
    __nv_bfloat16* oh = xh + (size_t)b * CC * SS;
    __nv_bfloat16* ol = xl + (size_t)b * CC * SS;
#pragma unroll
    for (int i = threadIdx.y; i < 32; i += 8) {
        float v = tile[threadIdx.x][i];
        __nv_bfloat16 h, l; split2(v, h, l);
        size_t o = (size_t)(c0 + i) * SS + t0 + threadIdx.x;
        oh[o] = h; ol[o] = l;
    }
}

// ---------------------------------------------------------------------------
// Row softmax over S=2048, output split to bf16 hi/lo
// ---------------------------------------------------------------------------
__global__ void __launch_bounds__(256) softmax_split_k(
    const float* __restrict__ score,
    __nv_bfloat16* __restrict__ ah, __nv_bfloat16* __restrict__ al)
{
    const float* p = score + (size_t)blockIdx.x * SS;
    const int tid = threadIdx.x;
    float v[8];
    float m = -1e30f;
#pragma unroll
    for (int i = 0; i < 8; i++) { v[i] = p[tid + i * 256]; m = fmaxf(m, v[i]); }
#pragma unroll
    for (int o = 16; o; o >>= 1) m = fmaxf(m, __shfl_xor_sync(0xffffffffu, m, o));
    __shared__ float red[8];
    if ((tid & 31) == 0) red[tid >> 5] = m;
    __syncthreads();
    m = red[0];
#pragma unroll
    for (int i = 1; i < 8; i++) m = fmaxf(m, red[i]);
    __syncthreads();
    float s = 0.0f;
#pragma unroll
    for (int i = 0; i < 8; i++) { v[i] = expf(v[i] - m); s += v[i]; }
#pragma unroll
    for (int o = 16; o; o >>= 1) s += __shfl_xor_sync(0xffffffffu, s, o);
    if ((tid & 31) == 0) red[tid >> 5] = s;
    __syncthreads();
    s = red[0];
#pragma unroll
    for (int i = 1; i < 8; i++) s += red[i];
    const float inv = 1.0f / s;
    __nv_bfloat16* oh = ah + (size_t)blockIdx.x * SS;
    __nv_bfloat16* ol = al + (size_t)blockIdx.x * SS;
#pragma unroll
    for (int i = 0; i < 8; i++) {
        float a = v[i] * inv;
        __nv_bfloat16 h, l; split2(a, h, l);
        oh[tid + i * 256] = h; ol[tid + i * 256] = l;
    }
}

// ---------------------------------------------------------------------------
// Launch
// ---------------------------------------------------------------------------
extern "C" void kernel_launch(void* const* d_in, const int* in_sizes, int n_in,
                              void* d_out, int out_size)
{
    const float* x    = (const float*)d_in[0];
    const float* xp   = (const float*)d_in[1];
    const float* W    = (const float*)d_in[2];
    const float* bias = (const float*)d_in[3];
    float* out = (float*)d_out;

    __nv_bfloat16 *txh, *txl, *xph, *xpl, *wh, *wl, *qh, *ql, *xth, *xtl, *ah, *al;
    float* score;
    cudaGetSymbolAddress((void**)&txh, g_txh); cudaGetSymbolAddress((void**)&txl, g_txl);
    cudaGetSymbolAddress((void**)&xph, g_xph); cudaGetSymbolAddress((void**)&xpl, g_xpl);
    cudaGetSymbolAddress((void**)&wh,  g_wh);  cudaGetSymbolAddress((void**)&wl,  g_wl);
    cudaGetSymbolAddress((void**)&qh,  g_qh);  cudaGetSymbolAddress((void**)&ql,  g_ql);
    cudaGetSymbolAddress((void**)&xth, g_xth); cudaGetSymbolAddress((void**)&xtl, g_xtl);
    cudaGetSymbolAddress((void**)&ah,  g_ah);  cudaGetSymbolAddress((void**)&al,  g_al);
    cudaGetSymbolAddress((void**)&score, g_score);

    cudaFuncSetAttribute(gemm_nt<0>, cudaFuncAttributeMaxDynamicSharedMemorySize, GEMM_SMEM);
    cudaFuncSetAttribute(gemm_nt<1>, cudaFuncAttributeMaxDynamicSharedMemorySize, GEMM_SMEM);
    cudaFuncSetAttribute(gemm_nt<2>, cudaFuncAttributeMaxDynamicSharedMemorySize, GEMM_SMEM);

    const int n = BB * SS * CC;
    split_xp_k<<<(n/4 + 255)/256, 256>>>((const float4*)xp,
        (__nv_bfloat162*)txh, (__nv_bfloat162*)txl,
        (__nv_bfloat162*)xph, (__nv_bfloat162*)xpl, n/4);
    split_w_k<<<(CC*CC/4 + 255)/256, 256>>>((const float4*)W,
        (__nv_bfloat162*)wh, (__nv_bfloat162*)wl, CC*CC/4);
    transpose_split_x<<<dim3(SS/32, CC/32, BB), dim3(32, 8)>>>(x, xth, xtl);

    // q = x' @ W^T + b  -> split bf16   (M=32768, N=512, K=512)
    gemm_nt<0><<<dim3(CC/TN, (BB*SS)/TM, 1), 256, GEMM_SMEM>>>(
        xph, xpl, wh, wl, nullptr, qh, ql, bias,
        BB*SS, CC, CC, 0, 0, 0);

    // score_b = tanh(x')_b @ q_b^T -> fp32   (M=N=2048, K=512, 16 batches)
    gemm_nt<1><<<dim3(SS/TN, SS/TM, BB), 256, GEMM_SMEM>>>(
        txh, txl, qh, ql, score, nullptr, nullptr, nullptr,
        SS, SS, CC, (long)SS*CC, (long)SS*CC, (long)SS*SS);

    softmax_split_k<<<BB*SS, 256>>>(score, ah, al);

    // y_b = alpha_b @ x_b  (via x^T, NT), tanh -> out   (M=2048, N=512, K=2048)
    gemm_nt<2><<<dim3(CC/TN, SS/TM, BB), 256, GEMM_SMEM>>>(
        ah, al, xth, xtl, out, nullptr, nullptr, nullptr,
        SS, CC, SS, (long)SS*SS, (long)CC*SS, (long)SS*CC);
}

// round 15
// speedup vs baseline: 1.0003x; 1.0003x over previous
#include <cuda_runtime.h>
#include <cuda_bf16.h>
#include <math.h>
#include <stdint.h>

#define BB 16
#define SS 2048
#define CC 512

// ---------------------------------------------------------------------------
// Device-global scratch (allocation-free per harness rules)
// ---------------------------------------------------------------------------
__device__ __nv_bfloat16 g_txh[BB*SS*CC], g_txl[BB*SS*CC];   // tanh(x') hi/lo
__device__ __nv_bfloat16 g_xph[BB*SS*CC], g_xpl[BB*SS*CC];   // x' hi/lo
__device__ __nv_bfloat16 g_wh[CC*CC],     g_wl[CC*CC];       // W hi/lo
__device__ __nv_bfloat16 g_qh[BB*SS*CC],  g_ql[BB*SS*CC];    // q hi/lo
__device__ __nv_bfloat16 g_xth[BB*SS*CC], g_xtl[BB*SS*CC];   // x^T hi/lo [b][c][t]
__device__ float         g_score[(size_t)BB*SS*SS];          // 268 MB
__device__ __nv_bfloat16 g_ah[(size_t)BB*SS*SS], g_al[(size_t)BB*SS*SS]; // alpha hi/lo

// ---------------------------------------------------------------------------
// PTX helpers (plain-sm_103-legal: ldmatrix, mma.sync, cp.async)
// ---------------------------------------------------------------------------
__device__ __forceinline__ uint32_t smem_u32(const void* p) {
    uint32_t a;
    asm("{ .reg .u64 t; cvta.to.shared.u64 t, %1; cvt.u32.u64 %0, t; }" : "=r"(a) : "l"(p));
    return a;
}
__device__ __forceinline__ void ldsm_x4(uint32_t* r, uint32_t addr) {
    asm volatile("ldmatrix.sync.aligned.m8n8.x4.shared.b16 {%0,%1,%2,%3}, [%4];"
        : "=r"(r[0]), "=r"(r[1]), "=r"(r[2]), "=r"(r[3]) : "r"(addr));
}
__device__ __forceinline__ void mma16816(float* d, const uint32_t* a, const uint32_t* b) {
    asm volatile(
        "mma.sync.aligned.m16n8k16.row.col.f32.bf16.bf16.f32 "
        "{%0,%1,%2,%3}, {%4,%5,%6,%7}, {%8,%9}, {%0,%1,%2,%3};"
        : "+f"(d[0]), "+f"(d[1]), "+f"(d[2]), "+f"(d[3])
        : "r"(a[0]), "r"(a[1]), "r"(a[2]), "r"(a[3]), "r"(b[0]), "r"(b[1]));
}
__device__ __forceinline__ void cp16(uint32_t s, const void* g) {
    asm volatile("cp.async.cg.shared.global [%0], [%1], 16;" :: "r"(s), "l"(g));
}
#define CP_COMMIT()  asm volatile("cp.async.commit_group;" ::: "memory")
#define CP_WAIT(n)   asm volatile("cp.async.wait_group %0;" :: "n"(n) : "memory")

// ---------------------------------------------------------------------------
// GEMM: C[M,N] = (Ah+Al)[M,K] * (Bh+Bl)[N,K]^T, bf16x3 (drop lo*lo), fp32 acc.
// CTA tile 128x128, K chunks of 32, double-buffered cp.async, 256 threads.
// Warps 4x2 -> 32x64 warp tile. B frags double-buffered in regs; MMA passes
// emitted pass-major so same-accumulator MMAs sit 4 independent issues apart.
// Rows padded to 40 bf16 (80B, conflict-free for ldmatrix).
// EPI: 0 = +bias then split to (Ch,Cl) bf16 ; 1 = fp32 to Cf ; 2 = tanh to Cf.
// ---------------------------------------------------------------------------
#define TM 128
#define TN 128
#define TK 32
#define ROWB 80                       // padded row bytes (40 bf16)
#define A_HALF (TM * ROWB)            // 10240
#define B_HALF (TN * ROWB)            // 10240
#define STAGE (2*A_HALF + 2*B_HALF)   // 40960
#define GEMM_SMEM (2 * STAGE)         // 81920

template<int EPI>
__global__ void __launch_bounds__(256, 2)
gemm_nt(const __nv_bfloat16* __restrict__ Ah, const __nv_bfloat16* __restrict__ Al,
        const __nv_bfloat16* __restrict__ Bh, const __nv_bfloat16* __restrict__ Bl,
        float* __restrict__ Cf,
        __nv_bfloat16* __restrict__ Ch, __nv_bfloat16* __restrict__ Cl,
        const float* __restrict__ bias,
        int M, int N, int K, long sA, long sB, long sC)
{
    extern __shared__ __align__(16) char smem[];
    const uint32_t sb = smem_u32(smem);

    const int tid = threadIdx.x;
    const long z = blockIdx.z;
    const int bm = blockIdx.y * TM;
    const int bn = blockIdx.x * TN;
    const __nv_bfloat16* Ahb = Ah + z * sA;
    const __nv_bfloat16* Alb = Al + z * sA;
    const __nv_bfloat16* Bhb = Bh + z * sB;
    const __nv_bfloat16* Blb = Bl + z * sB;

    // --- async stage loader: 8 x 16B per thread ---
    auto load_stage = [&](int kk, int s) {
        const uint32_t st = sb + s * STAGE;
#pragma unroll
        for (int i = 0; i < 4; i++) {                 // A hi/lo: 1024 chunks
            int idx = tid + i * 256;
            int half = idx >> 9;
            int row  = (idx & 511) >> 2;
            int ch   = idx & 3;
            const __nv_bfloat16* src =
                (half ? Alb : Ahb) + (long)(bm + row) * K + kk + ch * 8;
            cp16(st + half * A_HALF + row * ROWB + ch * 16, src);
        }
#pragma unroll
        for (int i = 0; i < 4; i++) {                 // B hi/lo: 1024 chunks
            int idx = tid + i * 256;
            int half = idx >> 9;
            int row  = (idx & 511) >> 2;
            int ch   = idx & 3;
            const __nv_bfloat16* src =
                (half ? Blb : Bhb) + (long)(bn + row) * K + kk + ch * 8;
            cp16(st + 2 * A_HALF + half * B_HALF + row * ROWB + ch * 16, src);
        }
    };

    const int w  = tid >> 5, l = tid & 31;
    const int wr = (w >> 1) * 32;        // warp row offset (4 rows of warps)
    const int wc = (w & 1) * 64;         // warp col offset (2 cols of warps)

    // lane-derived ldmatrix offsets
    const uint32_t a_loff = (l & 15) * ROWB + (l >> 4) * 16;
    const uint32_t b_loff = (((l >> 4) & 1) * 8 + (l & 7)) * ROWB + ((l >> 3) & 1) * 16;

    float acc[2][8][4];
#pragma unroll
    for (int mi = 0; mi < 2; mi++)
#pragma unroll
        for (int ni = 0; ni < 8; ni++)
#pragma unroll
            for (int j = 0; j < 4; j++) acc[mi][ni][j] = 0.0f;

    const int nc = K / TK;
    load_stage(0, 0);
    CP_COMMIT();

    for (int c = 0; c < nc; c++) {
        if (c + 1 < nc) {
            load_stage((c + 1) * TK, (c + 1) & 1);
            CP_COMMIT();
            CP_WAIT(1);
        } else {
            CP_WAIT(0);
        }
        __syncthreads();

        const uint32_t st = sb + (c & 1) * STAGE;
        const uint32_t a_h = st + (wr * ROWB) + a_loff;
        const uint32_t a_l = a_h + A_HALF;
        const uint32_t b_h = st + 2 * A_HALF + (wc * ROWB) + b_loff;
        const uint32_t b_l = b_h + B_HALF;

#pragma unroll
        for (int ks = 0; ks < 2; ks++) {
            uint32_t ah[2][4], al[2][4];
#pragma unroll
            for (int mi = 0; mi < 2; mi++) {
                ldsm_x4(ah[mi], a_h + mi * 16 * ROWB + ks * 32);
                ldsm_x4(al[mi], a_l + mi * 16 * ROWB + ks * 32);
            }
            // B fragments double-buffered across the 4 n16 groups
            uint32_t bh[2][4], bl[2][4];
            ldsm_x4(bh[0], b_h + ks * 32);
            ldsm_x4(bl[0], b_l + ks * 32);
#pragma unroll
            for (int p = 0; p < 4; p++) {
                const int cur = p & 1, nxt = cur ^ 1;
                if (p + 1 < 4) {
                    ldsm_x4(bh[nxt], b_h + (p + 1) * 16 * ROWB + ks * 32);
                    ldsm_x4(bl[nxt], b_l + (p + 1) * 16 * ROWB + ks * 32);
                }
                // pass-major: same-acc MMAs are 4 independent issues apart
#pragma unroll
                for (int s2 = 0; s2 < 2; s2++)            // hi*hi
#pragma unroll
                    for (int mi = 0; mi < 2; mi++)
                        mma16816(acc[mi][p * 2 + s2], ah[mi], &bh[cur][s2 * 2]);
#pragma unroll
                for (int s2 = 0; s2 < 2; s2++)            // hi*lo
#pragma unroll
                    for (int mi = 0; mi < 2; mi++)
                        mma16816(acc[mi][p * 2 + s2], ah[mi], &bl[cur][s2 * 2]);
#pragma unroll
                for (int s2 = 0; s2 < 2; s2++)            // lo*hi
#pragma unroll
                    for (int mi = 0; mi < 2; mi++)
                        mma16816(acc[mi][p * 2 + s2], al[mi], &bh[cur][s2 * 2]);
            }
        }
        __syncthreads();
    }

    // --- epilogue ---
#pragma unroll
    for (int mi = 0; mi < 2; mi++)
#pragma unroll
        for (int ni = 0; ni < 8; ni++) {
            const float* d = acc[mi][ni];
            const int r0 = bm + wr + mi * 16 + (l >> 2);
            const int c0 = bn + wc + ni * 8 + (l & 3) * 2;
#pragma unroll
            for (int h = 0; h < 2; h++) {
                const int row = r0 + h * 8;
                float v0 = d[h * 2], v1 = d[h * 2 + 1];
                if (EPI == 0) {
                    v0 += bias[c0]; v1 += bias[c0 + 1];
                    __nv_bfloat162 hp, lp;
                    hp.x = __float2bfloat16(v0);
                    hp.y = __float2bfloat16(v1);
                    lp.x = __float2bfloat16(v0 - __bfloat162float(hp.x));
                    lp.y = __float2bfloat16(v1 - __bfloat162float(hp.y));
                    long o = z * sC + (long)row * N + c0;
                    *(__nv_bfloat162*)(Ch + o) = hp;
                    *(__nv_bfloat162*)(Cl + o) = lp;
                } else {
                    if (EPI == 2) { v0 = tanhf(v0); v1 = tanhf(v1); }
                    *(float2*)(Cf + z * sC + (long)row * N + c0) = make_float2(v0, v1);
                }
            }
        }
}

// ---------------------------------------------------------------------------
// Elementwise splits
// ---------------------------------------------------------------------------
__device__ __forceinline__ void split2(float v, __nv_bfloat16& h, __nv_bfloat16& l) {
    h = __float2bfloat16(v);
    l = __float2bfloat16(v - __bfloat162float(h));
}

__global__ void split_xp_k(const float4* __restrict__ xp,
                           __nv_bfloat162* th, __nv_bfloat162* tl,
                           __nv_bfloat162* xh, __nv_bfloat162* xl, int n4)
{
    int i = blockIdx.x * blockDim.x + threadIdx.x;
    if (i >= n4) return;
    float4 v = xp[i];
    __nv_bfloat162 a, b;
    split2(v.x, a.x, b.x); split2(v.y, a.y, b.y); xh[2*i] = a; xl[2*i] = b;
    split2(v.z, a.x, b.x); split2(v.w, a.y, b.y); xh[2*i+1] = a; xl[2*i+1] = b;
    float4 t = make_float4(tanhf(v.x), tanhf(v.y), tanhf(v.z), tanhf(v.w));
    split2(t.x, a.x, b.x); split2(t.y, a.y, b.y); th[2*i] = a; tl[2*i] = b;
    split2(t.z, a.x, b.x); split2(t.w, a.y, b.y); th[2*i+1] = a; tl[2*i+1] = b;
}

__global__ void split_w_k(const float4* __restrict__ w,
                          __nv_bfloat162* wh, __nv_bfloat162* wl, int n4)
{
    int i = blockIdx.x * blockDim.x + threadIdx.x;
    if (i >= n4) return;
    float4 v = w[i];
    __nv_bfloat162 a, b;
    split2(v.x, a.x, b.x); split2(v.y, a.y, b.y); wh[2*i] = a; wl[2*i] = b;
    split2(v.z, a.x, b.x); split2(v.w, a.y, b.y); wh[2*i+1] = a; wl[2*i+1] = b;
}

// x[b][t][c] -> xT[b][c][t] hi/lo
__global__ void transpose_split_x(const float* __restrict__ x,
                                  __nv_bfloat16* __restrict__ xh,
                                  __nv_bfloat16* __restrict__ xl)
{
    __shared__ float tile[32][33];
    const int b = blockIdx.z;
    const int t0 = blockIdx.x * 32, c0 = blockIdx.y * 32;
    const float* xb = x + (size_t)b * SS * CC;
#pragma unroll
    for (int i = threadIdx.y; i < 32; i += 8)
        tile[i][threadIdx.x] = xb[(size_t)(t0 + i) * CC + c0 + threadIdx.x];
    __syncthreads();
    __nv_bfloat16* oh = xh + (size_t)b * CC * SS;
    __nv_bfloat16* ol = xl + (size_t)b * CC * SS;
#pragma unroll
    for (int i = threadIdx.y; i < 32; i += 8) {
        float v = tile[threadIdx.x][i];
        __nv_bfloat16 h, l; split2(v, h, l);
        size_t o = (size_t)(c0 + i) * SS + t0 + threadIdx.x;
        oh[o] = h; ol[o] = l;
    }
}

// ---------------------------------------------------------------------------
// Row softmax over S=2048, output split to bf16 hi/lo
// ---------------------------------------------------------------------------
__global__ void __launch_bounds__(256) softmax_split_k(
    const float* __restrict__ score,
    __nv_bfloat16* __restrict__ ah, __nv_bfloat16* __restrict__ al)
{
    const float* p = score + (size_t)blockIdx.x * SS;
    const int tid = threadIdx.x;
    float v[8];
    float m = -1e30f;
#pragma unroll
    for (int i = 0; i < 8; i++) { v[i] = p[tid + i * 256]; m = fmaxf(m, v[i]); }
#pragma unroll
    for (int o = 16; o; o >>= 1) m = fmaxf(m, __shfl_xor_sync(0xffffffffu, m, o));
    __shared__ float red[8];
    if ((tid & 31) == 0) red[tid >> 5] = m;
    __syncthreads();
    m = red[0];
#pragma unroll
    for (int i = 1; i < 8; i++) m = fmaxf(m, red[i]);
    __syncthreads();
    float s = 0.0f;
#pragma unroll
    for (int i = 0; i < 8; i++) { v[i] = expf(v[i] - m); s += v[i]; }
#pragma unroll
    for (int o = 16; o; o >>= 1) s += __shfl_xor_sync(0xffffffffu, s, o);
    if ((tid & 31) == 0) red[tid >> 5] = s;
    __syncthreads();
    s = red[0];
#pragma unroll
    for (int i = 1; i < 8; i++) s += red[i];
    const float inv = 1.0f / s;
    __nv_bfloat16* oh = ah + (size_t)blockIdx.x * SS;
    __nv_bfloat16* ol = al + (size_t)blockIdx.x * SS;
#pragma unroll
    for (int i = 0; i < 8; i++) {
        float a = v[i] * inv;
        __nv_bfloat16 h, l; split2(a, h, l);
        oh[tid + i * 256] = h; ol[tid + i * 256] = l;
    }
}

// ---------------------------------------------------------------------------
// Launch
// ---------------------------------------------------------------------------
extern "C" void kernel_launch(void* const* d_in, const int* in_sizes, int n_in,
                              void* d_out, int out_size)
{
    const float* x    = (const float*)d_in[0];
    const float* xp   = (const float*)d_in[1];
    const float* W    = (const float*)d_in[2];
    const float* bias = (const float*)d_in[3];
    float* out = (float*)d_out;

    __nv_bfloat16 *txh, *txl, *xph, *xpl, *wh, *wl, *qh, *ql, *xth, *xtl, *ah, *al;
    float* score;
    cudaGetSymbolAddress((void**)&txh, g_txh); cudaGetSymbolAddress((void**)&txl, g_txl);
    cudaGetSymbolAddress((void**)&xph, g_xph); cudaGetSymbolAddress((void**)&xpl, g_xpl);
    cudaGetSymbolAddress((void**)&wh,  g_wh);  cudaGetSymbolAddress((void**)&wl,  g_wl);
    cudaGetSymbolAddress((void**)&qh,  g_qh);  cudaGetSymbolAddress((void**)&ql,  g_ql);
    cudaGetSymbolAddress((void**)&xth, g_xth); cudaGetSymbolAddress((void**)&xtl, g_xtl);
    cudaGetSymbolAddress((void**)&ah,  g_ah);  cudaGetSymbolAddress((void**)&al,  g_al);
    cudaGetSymbolAddress((void**)&score, g_score);

    cudaFuncSetAttribute(gemm_nt<0>, cudaFuncAttributeMaxDynamicSharedMemorySize, GEMM_SMEM);
    cudaFuncSetAttribute(gemm_nt<1>, cudaFuncAttributeMaxDynamicSharedMemorySize, GEMM_SMEM);
    cudaFuncSetAttribute(gemm_nt<2>, cudaFuncAttributeMaxDynamicSharedMemorySize, GEMM_SMEM);

    const int n = BB * SS * CC;
    split_xp_k<<<(n/4 + 255)/256, 256>>>((const float4*)xp,
        (__nv_bfloat162*)txh, (__nv_bfloat162*)txl,
        (__nv_bfloat162*)xph, (__nv_bfloat162*)xpl, n/4);
    split_w_k<<<(CC*CC/4 + 255)/256, 256>>>((const float4*)W,
        (__nv_bfloat162*)wh, (__nv_bfloat162*)wl, CC*CC/4);
    transpose_split_x<<<dim3(SS/32, CC/32, BB), dim3(32, 8)>>>(x, xth, xtl);

    // q = x' @ W^T + b  -> split bf16   (M=32768, N=512, K=512)
    gemm_nt<0><<<dim3(CC/TN, (BB*SS)/TM, 1), 256, GEMM_SMEM>>>(
        xph, xpl, wh, wl, nullptr, qh, ql, bias,
        BB*SS, CC, CC, 0, 0, 0);

    // score_b = tanh(x')_b @ q_b^T -> fp32   (M=N=2048, K=512, 16 batches)
    gemm_nt<1><<<dim3(SS/TN, SS/TM, BB), 256, GEMM_SMEM>>>(
        txh, txl, qh, ql, score, nullptr, nullptr, nullptr,
        SS, SS, CC, (long)SS*CC, (long)SS*CC, (long)SS*SS);

    softmax_split_k<<<BB*SS, 256>>>(score, ah, al);

    // y_b = alpha_b @ x_b  (via x^T, NT), tanh -> out   (M=2048, N=512, K=2048)
    gemm_nt<2><<<dim3(CC/TN, SS/TM, BB), 256, GEMM_SMEM>>>(
        ah, al, xth, xtl, out, nullptr, nullptr, nullptr,
        SS, CC, SS, (long)SS*SS, (long)CC*SS, (long)SS*CC);
}

// round 16
// speedup vs baseline: 1.0011x; 1.0007x over previous
#include <cuda_runtime.h>
#include <cuda_bf16.h>
#include <math.h>
#include <stdint.h>

#define BB 16
#define SS 2048
#define CC 512

// ---------------------------------------------------------------------------
// Device-global scratch (allocation-free per harness rules)
// ---------------------------------------------------------------------------
__device__ __nv_bfloat16 g_txh[BB*SS*CC], g_txl[BB*SS*CC];   // tanh(x') hi/lo
__device__ __nv_bfloat16 g_xph[BB*SS*CC], g_xpl[BB*SS*CC];   // x' hi/lo
__device__ __nv_bfloat16 g_wh[CC*CC],     g_wl[CC*CC];       // W hi/lo
__device__ __nv_bfloat16 g_qh[BB*SS*CC],  g_ql[BB*SS*CC];    // q hi/lo
__device__ __nv_bfloat16 g_xth[BB*SS*CC], g_xtl[BB*SS*CC];   // x^T hi/lo [b][c][t]
__device__ float         g_score[(size_t)BB*SS*SS];          // 268 MB
__device__ __nv_bfloat16 g_ah[(size_t)BB*SS*SS], g_al[(size_t)BB*SS*SS]; // alpha hi/lo

// ---------------------------------------------------------------------------
// PTX helpers (plain-sm_103-legal: ldmatrix, mma.sync, cp.async)
// ---------------------------------------------------------------------------
__device__ __forceinline__ uint32_t smem_u32(const void* p) {
    uint32_t a;
    asm("{ .reg .u64 t; cvta.to.shared.u64 t, %1; cvt.u32.u64 %0, t; }" : "=r"(a) : "l"(p));
    return a;
}
__device__ __forceinline__ void ldsm_x4(uint32_t* r, uint32_t addr) {
    asm volatile("ldmatrix.sync.aligned.m8n8.x4.shared.b16 {%0,%1,%2,%3}, [%4];"
        : "=r"(r[0]), "=r"(r[1]), "=r"(r[2]), "=r"(r[3]) : "r"(addr));
}
__device__ __forceinline__ void mma16816(float* d, const uint32_t* a, const uint32_t* b) {
    asm volatile(
        "mma.sync.aligned.m16n8k16.row.col.f32.bf16.bf16.f32 "
        "{%0,%1,%2,%3}, {%4,%5,%6,%7}, {%8,%9}, {%0,%1,%2,%3};"
        : "+f"(d[0]), "+f"(d[1]), "+f"(d[2]), "+f"(d[3])
        : "r"(a[0]), "r"(a[1]), "r"(a[2]), "r"(a[3]), "r"(b[0]), "r"(b[1]));
}
__device__ __forceinline__ void cp16(uint32_t s, const void* g) {
    asm volatile("cp.async.cg.shared.global [%0], [%1], 16;" :: "r"(s), "l"(g));
}
#define CP_COMMIT()  asm volatile("cp.async.commit_group;" ::: "memory")
#define CP_WAIT(n)   asm volatile("cp.async.wait_group %0;" :: "n"(n) : "memory")

// ---------------------------------------------------------------------------
// GEMM: C[M,N] = (Ah+Al)[M,K] * (Bh+Bl)[N,K]^T, bf16x3 (drop lo*lo), fp32 acc.
// CTA tile 128x128, K chunks of 32, double-buffered cp.async, 256 threads.
// Warps 4x2 -> 32x64 warp tile. B frags double-buffered in regs; MMA passes
// emitted pass-major so same-accumulator MMAs sit 4 independent issues apart.
// Rows padded to 40 bf16 (80B, conflict-free for ldmatrix).
// EPI: 0 = +bias then split to (Ch,Cl) bf16 ; 1 = fp32 to Cf ; 2 = tanh to Cf.
// ---------------------------------------------------------------------------
#define TM 128
#define TN 128
#define TK 32
#define ROWB 80                       // padded row bytes (40 bf16)
#define A_HALF (TM * ROWB)            // 10240
#define B_HALF (TN * ROWB)            // 10240
#define STAGE (2*A_HALF + 2*B_HALF)   // 40960
#define GEMM_SMEM (2 * STAGE)         // 81920

template<int EPI>
__global__ void __launch_bounds__(256, 2)
gemm_nt(const __nv_bfloat16* __restrict__ Ah, const __nv_bfloat16* __restrict__ Al,
        const __nv_bfloat16* __restrict__ Bh, const __nv_bfloat16* __restrict__ Bl,
        float* __restrict__ Cf,
        __nv_bfloat16* __restrict__ Ch, __nv_bfloat16* __restrict__ Cl,
        const float* __restrict__ bias,
        int M, int N, int K, long sA, long sB, long sC)
{
    extern __shared__ __align__(16) char smem[];
    const uint32_t sb = smem_u32(smem);

    const int tid = threadIdx.x;
    const long z = blockIdx.z;
    const int bm = blockIdx.y * TM;
    const int bn = blockIdx.x * TN;
    const __nv_bfloat16* Ahb = Ah + z * sA;
    const __nv_bfloat16* Alb = Al + z * sA;
    const __nv_bfloat16* Bhb = Bh + z * sB;
    const __nv_bfloat16* Blb = Bl + z * sB;

    // --- async stage loader: 8 x 16B per thread ---
    auto load_stage = [&](int kk, int s) {
        const uint32_t st = sb + s * STAGE;
#pragma unroll
        for (int i = 0; i < 4; i++) {                 // A hi/lo: 1024 chunks
            int idx = tid + i * 256;
            int half = idx >> 9;
            int row  = (idx & 511) >> 2;
            int ch   = idx & 3;
            const __nv_bfloat16* src =
                (half ? Alb : Ahb) + (long)(bm + row) * K + kk + ch * 8;
            cp16(st + half * A_HALF + row * ROWB + ch * 16, src);
        }
#pragma unroll
        for (int i = 0; i < 4; i++) {                 // B hi/lo: 1024 chunks
            int idx = tid + i * 256;
            int half = idx >> 9;
            int row  = (idx & 511) >> 2;
            int ch   = idx & 3;
            const __nv_bfloat16* src =
                (half ? Blb : Bhb) + (long)(bn + row) * K + kk + ch * 8;
            cp16(st + 2 * A_HALF + half * B_HALF + row * ROWB + ch * 16, src);
        }
    };

    const int w  = tid >> 5, l = tid & 31;
    const int wr = (w >> 1) * 32;        // warp row offset (4 rows of warps)
    const int wc = (w & 1) * 64;         // warp col offset (2 cols of warps)

    // lane-derived ldmatrix offsets
    const uint32_t a_loff = (l & 15) * ROWB + (l >> 4) * 16;
    const uint32_t b_loff = (((l >> 4) & 1) * 8 + (l & 7)) * ROWB + ((l >> 3) & 1) * 16;

    float acc[2][8][4];
#pragma unroll
    for (int mi = 0; mi < 2; mi++)
#pragma unroll
        for (int ni = 0; ni < 8; ni++)
#pragma unroll
            for (int j = 0; j < 4; j++) acc[mi][ni][j] = 0.0f;

    const int nc = K / TK;
    load_stage(0, 0);
    CP_COMMIT();

    for (int c = 0; c < nc; c++) {
        if (c + 1 < nc) {
            load_stage((c + 1) * TK, (c + 1) & 1);
            CP_COMMIT();
            CP_WAIT(1);
        } else {
            CP_WAIT(0);
        }
        __syncthreads();

        const uint32_t st = sb + (c & 1) * STAGE;
        const uint32_t a_h = st + (wr * ROWB) + a_loff;
        const uint32_t a_l = a_h + A_HALF;
        const uint32_t b_h = st + 2 * A_HALF + (wc * ROWB) + b_loff;
        const uint32_t b_l = b_h + B_HALF;

#pragma unroll
        for (int ks = 0; ks < 2; ks++) {
            uint32_t ah[2][4], al[2][4];
#pragma unroll
            for (int mi = 0; mi < 2; mi++) {
                ldsm_x4(ah[mi], a_h + mi * 16 * ROWB + ks * 32);
                ldsm_x4(al[mi], a_l + mi * 16 * ROWB + ks * 32);
            }
            // B fragments double-buffered across the 4 n16 groups
            uint32_t bh[2][4], bl[2][4];
            ldsm_x4(bh[0], b_h + ks * 32);
            ldsm_x4(bl[0], b_l + ks * 32);
#pragma unroll
            for (int p = 0; p < 4; p++) {
                const int cur = p & 1, nxt = cur ^ 1;
                if (p + 1 < 4) {
                    ldsm_x4(bh[nxt], b_h + (p + 1) * 16 * ROWB + ks * 32);
                    ldsm_x4(bl[nxt], b_l + (p + 1) * 16 * ROWB + ks * 32);
                }
                // pass-major: same-acc MMAs are 4 independent issues apart
#pragma unroll
                for (int s2 = 0; s2 < 2; s2++)            // hi*hi
#pragma unroll
                    for (int mi = 0; mi < 2; mi++)
                        mma16816(acc[mi][p * 2 + s2], ah[mi], &bh[cur][s2 * 2]);
#pragma unroll
                for (int s2 = 0; s2 < 2; s2++)            // hi*lo
#pragma unroll
                    for (int mi = 0; mi < 2; mi++)
                        mma16816(acc[mi][p * 2 + s2], ah[mi], &bl[cur][s2 * 2]);
#pragma unroll
                for (int s2 = 0; s2 < 2; s2++)            // lo*hi
#pragma unroll
                    for (int mi = 0; mi < 2; mi++)
                        mma16816(acc[mi][p * 2 + s2], al[mi], &bh[cur][s2 * 2]);
            }
        }
        __syncthreads();
    }

    // --- epilogue ---
#pragma unroll
    for (int mi = 0; mi < 2; mi++)
#pragma unroll
        for (int ni = 0; ni < 8; ni++) {
            const float* d = acc[mi][ni];
            const int r0 = bm + wr + mi * 16 + (l >> 2);
            const int c0 = bn + wc + ni * 8 + (l & 3) * 2;
#pragma unroll
            for (int h = 0; h < 2; h++) {
                const int row = r0 + h * 8;
                float v0 = d[h * 2], v1 = d[h * 2 + 1];
                if (EPI == 0) {
                    v0 += bias[c0]; v1 += bias[c0 + 1];
                    __nv_bfloat162 hp, lp;
                    hp.x = __float2bfloat16(v0);
                    hp.y = __float2bfloat16(v1);
                    lp.x = __float2bfloat16(v0 - __bfloat162float(hp.x));
                    lp.y = __float2bfloat16(v1 - __bfloat162float(hp.y));
                    long o = z * sC + (long)row * N + c0;
                    *(__nv_bfloat162*)(Ch + o) = hp;
                    *(__nv_bfloat162*)(Cl + o) = lp;
                } else {
                    if (EPI == 2) { v0 = tanhf(v0); v1 = tanhf(v1); }
                    *(float2*)(Cf + z * sC + (long)row * N + c0) = make_float2(v0, v1);
                }
            }
        }
}

// ---------------------------------------------------------------------------
// Elementwise splits
// ---------------------------------------------------------------------------
__device__ __forceinline__ void split2(float v, __nv_bfloat16& h, __nv_bfloat16& l) {
    h = __float2bfloat16(v);
    l = __float2bfloat16(v - __bfloat162float(h));
}

__global__ void split_xp_k(const float4* __restrict__ xp,
                           __nv_bfloat162* th, __nv_bfloat162* tl,
                           __nv_bfloat162* xh, __nv_bfloat162* xl, int n4)
{
    int i = blockIdx.x * blockDim.x + threadIdx.x;
    if (i >= n4) return;
    float4 v = xp[i];
    __nv_bfloat162 a, b;
    split2(v.x, a.x, b.x); split2(v.y, a.y, b.y); xh[2*i] = a; xl[2*i] = b;
    split2(v.z, a.x, b.x); split2(v.w, a.y, b.y); xh[2*i+1] = a; xl[2*i+1] = b;
    float4 t = make_float4(tanhf(v.x), tanhf(v.y), tanhf(v.z), tanhf(v.w));
    split2(t.x, a.x, b.x); split2(t.y, a.y, b.y); th[2*i] = a; tl[2*i] = b;
    split2(t.z, a.x, b.x); split2(t.w, a.y, b.y); th[2*i+1] = a; tl[2*i+1] = b;
}

__global__ void split_w_k(const float4* __restrict__ w,
                          __nv_bfloat162* wh, __nv_bfloat162* wl, int n4)
{
    int i = blockIdx.x * blockDim.x + threadIdx.x;
    if (i >= n4) return;
    float4 v = w[i];
    __nv_bfloat162 a, b;
    split2(v.x, a.x, b.x); split2(v.y, a.y, b.y); wh[2*i] = a; wl[2*i] = b;
    split2(v.z, a.x, b.x); split2(v.w, a.y, b.y); wh[2*i+1] = a; wl[2*i+1] = b;
}

// x[b][t][c] -> xT[b][c][t] hi/lo
__global__ void transpose_split_x(const float* __restrict__ x,
                                  __nv_bfloat16* __restrict__ xh,
                                  __nv_bfloat16* __restrict__ xl)
{
    __shared__ float tile[32][33];
    const int b = blockIdx.z;
    const int t0 = blockIdx.x * 32, c0 = blockIdx.y * 32;
    const float* xb = x + (size_t)b * SS * CC;
#pragma unroll
    for (int i = threadIdx.y; i < 32; i += 8)
        tile[i][threadIdx.x] = xb[(size_t)(t0 + i) * CC + c0 + threadIdx.x];
    __syncthreads();
    __nv_bfloat16* oh = xh + (size_t)b * CC * SS;
    __nv_bfloat16* ol = xl + (size_t)b * CC * SS;
#pragma unroll
    for (int i = threadIdx.y; i < 32; i += 8) {
        float v = tile[threadIdx.x][i];
        __nv_bfloat16 h, l; split2(v, h, l);
        size_t o = (size_t)(c0 + i) * SS + t0 + threadIdx.x;
        oh[o] = h; ol[o] = l;
    }
}

// ---------------------------------------------------------------------------
// Row softmax over S=2048, output split to bf16 hi/lo
// ---------------------------------------------------------------------------
__global__ void __launch_bounds__(256) softmax_split_k(
    const float* __restrict__ score,
    __nv_bfloat16* __restrict__ ah, __nv_bfloat16* __restrict__ al)
{
    const float* p = score + (size_t)blockIdx.x * SS;
    const int tid = threadIdx.x;
    float v[8];
    float m = -1e30f;
#pragma unroll
    for (int i = 0; i < 8; i++) { v[i] = p[tid + i * 256]; m = fmaxf(m, v[i]); }
#pragma unroll
    for (int o = 16; o; o >>= 1) m = fmaxf(m, __shfl_xor_sync(0xffffffffu, m, o));
    __shared__ float red[8];
    if ((tid & 31) == 0) red[tid >> 5] = m;
    __syncthreads();
    m = red[0];
#pragma unroll
    for (int i = 1; i < 8; i++) m = fmaxf(m, red[i]);
    __syncthreads();
    float s = 0.0f;
#pragma unroll
    for (int i = 0; i < 8; i++) { v[i] = expf(v[i] - m); s += v[i]; }
#pragma unroll
    for (int o = 16; o; o >>= 1) s += __shfl_xor_sync(0xffffffffu, s, o);
    if ((tid & 31) == 0) red[tid >> 5] = s;
    __syncthreads();
    s = red[0];
#pragma unroll
    for (int i = 1; i < 8; i++) s += red[i];
    const float inv = 1.0f / s;
    __nv_bfloat16* oh = ah + (size_t)blockIdx.x * SS;
    __nv_bfloat16* ol = al + (size_t)blockIdx.x * SS;
#pragma unroll
    for (int i = 0; i < 8; i++) {
        float a = v[i] * inv;
        __nv_bfloat16 h, l; split2(a, h, l);
        oh[tid + i * 256] = h; ol[tid + i * 256] = l;
    }
}

// ---------------------------------------------------------------------------
// Launch
// ---------------------------------------------------------------------------
extern "C" void kernel_launch(void* const* d_in, const int* in_sizes, int n_in,
                              void* d_out, int out_size)
{
    const float* x    = (const float*)d_in[0];
    const float* xp   = (const float*)d_in[1];
    const float* W    = (const float*)d_in[2];
    const float* bias = (const float*)d_in[3];
    float* out = (float*)d_out;

    __nv_bfloat16 *txh, *txl, *xph, *xpl, *wh, *wl, *qh, *ql, *xth, *xtl, *ah, *al;
    float* score;
    cudaGetSymbolAddress((void**)&txh, g_txh); cudaGetSymbolAddress((void**)&txl, g_txl);
    cudaGetSymbolAddress((void**)&xph, g_xph); cudaGetSymbolAddress((void**)&xpl, g_xpl);
    cudaGetSymbolAddress((void**)&wh,  g_wh);  cudaGetSymbolAddress((void**)&wl,  g_wl);
    cudaGetSymbolAddress((void**)&qh,  g_qh);  cudaGetSymbolAddress((void**)&ql,  g_ql);
    cudaGetSymbolAddress((void**)&xth, g_xth); cudaGetSymbolAddress((void**)&xtl, g_xtl);
    cudaGetSymbolAddress((void**)&ah,  g_ah);  cudaGetSymbolAddress((void**)&al,  g_al);
    cudaGetSymbolAddress((void**)&score, g_score);

    cudaFuncSetAttribute(gemm_nt<0>, cudaFuncAttributeMaxDynamicSharedMemorySize, GEMM_SMEM);
    cudaFuncSetAttribute(gemm_nt<1>, cudaFuncAttributeMaxDynamicSharedMemorySize, GEMM_SMEM);
    cudaFuncSetAttribute(gemm_nt<2>, cudaFuncAttributeMaxDynamicSharedMemorySize, GEMM_SMEM);

    const int n = BB * SS * CC;
    split_xp_k<<<(n/4 + 255)/256, 256>>>((const float4*)xp,
        (__nv_bfloat162*)txh, (__nv_bfloat162*)txl,
        (__nv_bfloat162*)xph, (__nv_bfloat162*)xpl, n/4);
    split_w_k<<<(CC*CC/4 + 255)/256, 256>>>((const float4*)W,
        (__nv_bfloat162*)wh, (__nv_bfloat162*)wl, CC*CC/4);
    transpose_split_x<<<dim3(SS/32, CC/32, BB), dim3(32, 8)>>>(x, xth, xtl);

    // q = x' @ W^T + b  -> split bf16   (M=32768, N=512, K=512)
    gemm_nt<0><<<dim3(CC/TN, (BB*SS)/TM, 1), 256, GEMM_SMEM>>>(
        xph, xpl, wh, wl, nullptr, qh, ql, bias,
        BB*SS, CC, CC, 0, 0, 0);

    // score_b = tanh(x')_b @ q_b^T -> fp32   (M=N=2048, K=512, 16 batches)
    gemm_nt<1><<<dim3(SS/TN, SS/TM, BB), 256, GEMM_SMEM>>>(
        txh, txl, qh, ql, score, nullptr, nullptr, nullptr,
        SS, SS, CC, (long)SS*CC, (long)SS*CC, (long)SS*SS);

    softmax_split_k<<<BB*SS, 256>>>(score, ah, al);

    // y_b = alpha_b @ x_b  (via x^T, NT), tanh -> out   (M=2048, N=512, K=2048)
    gemm_nt<2><<<dim3(CC/TN, SS/TM, BB), 256, GEMM_SMEM>>>(
        ah, al, xth, xtl, out, nullptr, nullptr, nullptr,
        SS, CC, SS, (long)SS*SS, (long)CC*SS, (long)SS*CC);
}